// round 1
// baseline (speedup 1.0000x reference)
#include <cuda_runtime.h>
#include <cuda_bf16.h>

// TripletSemihardLoss — N x D embeddings (f32), N labels (int32 or int64; autodetected).
// Output: scalar f32 loss.
//
// Pipeline:
//   K1: sq[i] = dot(e_i, e_i); zero accumulators; detect label word width
//   K2: d[i,k] = sqrt(max(sq_i + sq_k - 2*e_i.e_k, EPS))   (tiled Gram)
//   K3: per-row semi-hard reduction; atomic accumulate numerator & denominator
//   K4: out = num / den

#define MAXN 1024
#define EPSV 1e-4f
#define MARGINV 1.0f

__device__ float g_d[MAXN * MAXN];
__device__ float g_sq[MAXN];
__device__ float g_acc[2];   // [0]=numerator, [1]=denominator
__device__ int   g_lab64;

// ---------------------------------------------------------------------------
// K1: row squared norms + init + label-dtype detection
// ---------------------------------------------------------------------------
__global__ void k_sq_init(const float* __restrict__ emb,
                          const unsigned int* __restrict__ labs,
                          int N, int D) {
    int gwarp = (blockIdx.x * blockDim.x + threadIdx.x) >> 5;
    int lane  = threadIdx.x & 31;

    if (blockIdx.x == 0 && threadIdx.x == 0) {
        g_acc[0] = 0.0f;
        g_acc[1] = 0.0f;
        // If labels are int64 (LE, values in [0,48)), every odd 32-bit word is 0.
        // Probe the first 8 odd words (safe for both layouts when N >= 16 ints).
        int is64 = 1;
        int nwords = 16;  // 64 bytes, < N*4 bytes for any N >= 16
        for (int w = 1; w < nwords; w += 2)
            if (labs[w] != 0u) is64 = 0;
        g_lab64 = is64;
    }

    if (gwarp < N) {
        const float* row = emb + (size_t)gwarp * D;
        float s = 0.0f;
        for (int t = lane; t < D; t += 32) {
            float v = row[t];
            s = fmaf(v, v, s);
        }
        #pragma unroll
        for (int o = 16; o > 0; o >>= 1)
            s += __shfl_down_sync(0xffffffffu, s, o);
        if (lane == 0) g_sq[gwarp] = s;
    }
}

// ---------------------------------------------------------------------------
// K2: pairwise distances via tiled Gram matrix. Block = 16x16 output tile.
// ---------------------------------------------------------------------------
__global__ void k_dist(const float* __restrict__ emb, int N, int D) {
    __shared__ float As[16][33];
    __shared__ float Bs[16][33];
    int tx = threadIdx.x, ty = threadIdx.y;
    int row = blockIdx.y * 16 + ty;
    int col = blockIdx.x * 16 + tx;
    int t = ty * 16 + tx;

    float acc = 0.0f;
    for (int kk = 0; kk < D; kk += 32) {
        #pragma unroll
        for (int e = t; e < 16 * 32; e += 256) {
            int r = e >> 5, c = e & 31;
            int gc = kk + c;
            int ga = blockIdx.y * 16 + r;
            int gb = blockIdx.x * 16 + r;
            As[r][c] = (ga < N && gc < D) ? emb[(size_t)ga * D + gc] : 0.0f;
            Bs[r][c] = (gb < N && gc < D) ? emb[(size_t)gb * D + gc] : 0.0f;
        }
        __syncthreads();
        #pragma unroll
        for (int c = 0; c < 32; c++)
            acc = fmaf(As[ty][c], Bs[tx][c], acc);
        __syncthreads();
    }

    if (row < N && col < N) {
        float v = (g_sq[row] + g_sq[col]) - 2.0f * acc;
        v = fmaxf(v, 0.0f);
        v = fmaxf(v, EPSV);
        g_d[row * N + col] = sqrtf(v);
    }
}

// ---------------------------------------------------------------------------
// K3: per-row semi-hard triplet reduction. One block per row i.
// ---------------------------------------------------------------------------
__global__ void __launch_bounds__(256) k_loss(const unsigned int* __restrict__ labs, int N) {
    __shared__ float r[MAXN];
    __shared__ unsigned char posf[MAXN];
    __shared__ int plist[MAXN];
    __shared__ int pcount;
    __shared__ float wmax[8], wmin[8];
    __shared__ float s_mx, s_mn, s_sum;

    const int i = blockIdx.x;
    const int tid = threadIdx.x;
    const int lane = tid & 31;
    const int warp = tid >> 5;
    const int nwarp = blockDim.x >> 5;
    const int is64 = g_lab64;
    const int li = labs[is64 ? 2 * i : i];

    if (tid == 0) { pcount = 0; s_sum = 0.0f; }
    __syncthreads();

    // Load d row + pos flags; build positive list; partial min/max.
    float lmx = -1e30f, lmn = 1e30f;
    for (int j = tid; j < N; j += blockDim.x) {
        float v = g_d[i * N + j];
        r[j] = v;
        int lj = labs[is64 ? 2 * j : j];
        int p = (lj == li) && (j != i);
        posf[j] = (unsigned char)p;
        if (p) {
            int idx = atomicAdd(&pcount, 1);
            plist[idx] = j;
        }
        lmx = fmaxf(lmx, v);
        lmn = fminf(lmn, v);
    }
    #pragma unroll
    for (int o = 16; o > 0; o >>= 1) {
        lmx = fmaxf(lmx, __shfl_down_sync(0xffffffffu, lmx, o));
        lmn = fminf(lmn, __shfl_down_sync(0xffffffffu, lmn, o));
    }
    if (lane == 0) { wmax[warp] = lmx; wmin[warp] = lmn; }
    __syncthreads();
    if (tid == 0) {
        float mx = wmax[0], mn = wmin[0];
        for (int w = 1; w < nwarp; w++) {
            mx = fmaxf(mx, wmax[w]);
            mn = fminf(mn, wmin[w]);
        }
        s_mx = mx;
        s_mn = mn;
    }
    __syncthreads();

    const float mx_d = s_mx;
    const float mn_d = s_mn;
    const int P = pcount;

    // One warp per positive anchor-positive pair (i,k).
    float warpsum = 0.0f;
    for (int p = warp; p < P; p += nwarp) {
        const int k = plist[p];
        const float c = r[k];
        const float mn_dd = c - mx_d;   // == min_j fl(c - r_j)  (monotone rounding)
        const float mx_dd = c - mn_d;   // == max_j fl(c - r_j)
        float m1 = 0.0f, m2 = 0.0f;
        unsigned anyv = 0u;
        for (int j = lane; j < N; j += 32) {
            float dd = c - r[j];
            int Mj = (posf[j] == 0);                 // (1 - pos), includes j == i
            int maskj = Mj && (dd < 0.0f);
            anyv |= (unsigned)maskj;
            m1 = fmaxf(m1, maskj ? (dd - mn_dd) : 0.0f);
            m2 = fminf(m2, Mj    ? (dd - mx_dd) : 0.0f);
        }
        anyv = __any_sync(0xffffffffu, anyv);
        #pragma unroll
        for (int o = 16; o > 0; o >>= 1) {
            m1 = fmaxf(m1, __shfl_down_sync(0xffffffffu, m1, o));
            m2 = fminf(m2, __shfl_down_sync(0xffffffffu, m2, o));
        }
        if (lane == 0) {
            float semi = anyv ? (m1 + mn_dd) : (m2 + mx_dd);
            warpsum += fmaxf(semi + MARGINV, 0.0f);
        }
    }
    if (lane == 0 && warpsum != 0.0f) atomicAdd(&s_sum, warpsum);
    __syncthreads();
    if (tid == 0) {
        atomicAdd(&g_acc[0], s_sum);
        atomicAdd(&g_acc[1], (float)P);
    }
}

// ---------------------------------------------------------------------------
// K4: final scalar
// ---------------------------------------------------------------------------
__global__ void k_final(float* __restrict__ out) {
    out[0] = g_acc[0] / g_acc[1];
}

// ---------------------------------------------------------------------------
extern "C" void kernel_launch(void* const* d_in, const int* in_sizes, int n_in,
                              void* d_out, int out_size) {
    const float* emb = (const float*)d_in[0];
    const unsigned int* labs = (const unsigned int*)d_in[1];
    float* out = (float*)d_out;

    const int N = in_sizes[1];
    const int D = in_sizes[0] / N;

    // K1: sq + init  (one warp per row)
    {
        int warps_needed = N;
        int threads = 128;                       // 4 warps per block
        int blocks = (warps_needed * 32 + threads - 1) / threads;
        k_sq_init<<<blocks, threads>>>(emb, labs, N, D);
    }
    // K2: distance matrix
    {
        dim3 block(16, 16);
        dim3 grid((N + 15) / 16, (N + 15) / 16);
        k_dist<<<grid, block>>>(emb, N, D);
    }
    // K3: per-row loss
    {
        k_loss<<<N, 256>>>(labs, N);
    }
    // K4: scalar
    k_final<<<1, 1>>>(out);
}